// round 1
// baseline (speedup 1.0000x reference)
#include <cuda_runtime.h>
#include <math.h>

#define BB   32
#define LL   2048
#define HH   512
#define H2   1024
#define VV   32000
#define LCH  32
#define LPB  (LL / LCH)          // 64 rows per chunk

// ---- scratch (device globals; all written deterministically each launch) ----
__device__ float g_partial[LCH][BB * H2];   // 32 x 32768 partial column sums (4 MB)
__device__ float g_cT[H2][BB];              // relu(mean) context, transposed
__device__ float g_hT[2][HH][BB];           // h transposed per direction
__device__ float g_logits[VV];
__device__ float g_pm[1024];
__device__ float g_ps[1024];

// =============== K1: partial column sums of encoder_out (256 MB stream) =====
__global__ void k1_partial(const float* __restrict__ enc) {
    int b  = blockIdx.x >> 5;          // /LCH
    int ch = blockIdx.x & (LCH - 1);
    int t  = threadIdx.x;              // 0..255 -> 256 float4 = 1024 floats/row
    const float4* p = (const float4*)enc + ((size_t)b * LL + (size_t)ch * LPB) * (H2 / 4);
    float4 a0 = make_float4(0.f, 0.f, 0.f, 0.f), a1 = a0, a2 = a0, a3 = a0;
    #pragma unroll 1
    for (int l = 0; l < LPB; l += 4) {
        float4 v0 = p[(size_t)(l + 0) * 256 + t];
        float4 v1 = p[(size_t)(l + 1) * 256 + t];
        float4 v2 = p[(size_t)(l + 2) * 256 + t];
        float4 v3 = p[(size_t)(l + 3) * 256 + t];
        a0.x += v0.x; a0.y += v0.y; a0.z += v0.z; a0.w += v0.w;
        a1.x += v1.x; a1.y += v1.y; a1.z += v1.z; a1.w += v1.w;
        a2.x += v2.x; a2.y += v2.y; a2.z += v2.z; a2.w += v2.w;
        a3.x += v3.x; a3.y += v3.y; a3.z += v3.z; a3.w += v3.w;
    }
    float4 s;
    s.x = (a0.x + a1.x) + (a2.x + a3.x);
    s.y = (a0.y + a1.y) + (a2.y + a3.y);
    s.z = (a0.z + a1.z) + (a2.z + a3.z);
    s.w = (a0.w + a1.w) + (a2.w + a3.w);
    ((float4*)(g_partial[ch] + b * H2))[t] = s;
}

// ====== K1b: finalize c (relu(mean), transposed), transpose h, fill attn ====
__global__ void k1b_finalize(const float* __restrict__ h, float* __restrict__ out) {
    int idx = blockIdx.x * 256 + threadIdx.x;      // 0..65535
    // attn_weights output: uniform 1/L
    out[VV + 2 * BB * HH + idx] = 1.0f / (float)LL;
    if (idx < BB * H2) {
        float s = 0.f;
        #pragma unroll
        for (int ch = 0; ch < LCH; ch++) s += g_partial[ch][idx];
        s *= (1.0f / (float)LL);
        if (s < 0.f) s = 0.f;
        int b = idx >> 10, d = idx & (H2 - 1);
        g_cT[d][b] = s;
        // transpose h: idx over [2][32][512]
        int dir = idx >> 14, bb = (idx >> 9) & 31, u = idx & (HH - 1);
        g_hT[dir][u][bb] = h[idx];
    }
}

// ============== K2: fused GRU (both directions), warp per (dir,u) ==========
__global__ void k2_gru(const float* __restrict__ h,
                       const float* __restrict__ Wihf, const float* __restrict__ Whhf,
                       const float* __restrict__ bihf, const float* __restrict__ bhhf,
                       const float* __restrict__ Wihb, const float* __restrict__ Whhb,
                       const float* __restrict__ bihb, const float* __restrict__ bhhb,
                       float* __restrict__ out) {
    int warp = (blockIdx.x * blockDim.x + threadIdx.x) >> 5;  // 0..1023
    int lane = threadIdx.x & 31;                              // lane = batch b
    int dir = warp >> 9;
    int u   = warp & (HH - 1);
    const float* Wih = dir ? Wihb : Wihf;
    const float* Whh = dir ? Whhb : Whhf;
    const float* bih = dir ? bihb : bihf;
    const float* bhh = dir ? bhhb : bhhf;

    float ar = bih[u], az = bih[HH + u], an = bih[2 * HH + u];
    {
        const float4* Wr = (const float4*)(Wih + (size_t)u * H2);
        const float4* Wz = (const float4*)(Wih + (size_t)(HH + u) * H2);
        const float4* Wn = (const float4*)(Wih + (size_t)(2 * HH + u) * H2);
        #pragma unroll 4
        for (int k4 = 0; k4 < H2 / 4; k4++) {
            float c0 = g_cT[k4 * 4 + 0][lane];
            float c1 = g_cT[k4 * 4 + 1][lane];
            float c2 = g_cT[k4 * 4 + 2][lane];
            float c3 = g_cT[k4 * 4 + 3][lane];
            float4 wr = Wr[k4], wz = Wz[k4], wn = Wn[k4];
            ar += c0 * wr.x + c1 * wr.y + c2 * wr.z + c3 * wr.w;
            az += c0 * wz.x + c1 * wz.y + c2 * wz.z + c3 * wz.w;
            an += c0 * wn.x + c1 * wn.y + c2 * wn.z + c3 * wn.w;
        }
    }
    float hr = bhh[u], hz = bhh[HH + u], hn = bhh[2 * HH + u];
    {
        const float4* Vr = (const float4*)(Whh + (size_t)u * HH);
        const float4* Vz = (const float4*)(Whh + (size_t)(HH + u) * HH);
        const float4* Vn = (const float4*)(Whh + (size_t)(2 * HH + u) * HH);
        #pragma unroll 4
        for (int k4 = 0; k4 < HH / 4; k4++) {
            float h0 = g_hT[dir][k4 * 4 + 0][lane];
            float h1 = g_hT[dir][k4 * 4 + 1][lane];
            float h2 = g_hT[dir][k4 * 4 + 2][lane];
            float h3 = g_hT[dir][k4 * 4 + 3][lane];
            float4 vr = Vr[k4], vz = Vz[k4], vn = Vn[k4];
            hr += h0 * vr.x + h1 * vr.y + h2 * vr.z + h3 * vr.w;
            hz += h0 * vz.x + h1 * vz.y + h2 * vz.z + h3 * vz.w;
            hn += h0 * vn.x + h1 * vn.y + h2 * vn.z + h3 * vn.w;
        }
    }
    float r = 1.f / (1.f + expf(-(ar + hr)));
    float z = 1.f / (1.f + expf(-(az + hz)));
    float n = tanhf(an + r * hn);
    float hold = h[dir * BB * HH + lane * HH + u];
    out[VV + dir * BB * HH + lane * HH + u] = (1.f - z) * n + z * hold;
}

// ===== K3a: logits GEMV (131 MB stream) + per-block online (max, sumexp) ====
__global__ void k3a_logits(const float* __restrict__ outW,
                           const float* __restrict__ outb,
                           const float* __restrict__ dout) {
    __shared__ float sv[H2];
    __shared__ float rl[32];
    int tid = threadIdx.x, lane = tid & 31, w = tid >> 5;
    // stage v = c_out[31] = [h_f[31], h_b[31]] from the h_new output region
    for (int i = tid; i < H2; i += 256) {
        int dir = i >> 9, uu = i & (HH - 1);
        sv[i] = dout[VV + dir * BB * HH + 31 * HH + uu];
    }
    __syncthreads();
    int r0 = blockIdx.x * 32 + w * 4;
    const float4* vp = (const float4*)sv;
    #pragma unroll 1
    for (int ri = 0; ri < 4; ri++) {
        int r = r0 + ri;
        const float4* wp = (const float4*)(outW + (size_t)r * H2);
        float acc = 0.f;
        #pragma unroll
        for (int i = 0; i < 8; i++) {
            float4 a = wp[i * 32 + lane];
            float4 v = vp[i * 32 + lane];
            acc += a.x * v.x + a.y * v.y + a.z * v.z + a.w * v.w;
        }
        #pragma unroll
        for (int o = 16; o; o >>= 1) acc += __shfl_down_sync(0xFFFFFFFFu, acc, o);
        if (lane == 0) {
            float lg = acc + outb[r];
            g_logits[r] = lg;
            rl[w * 4 + ri] = lg;
        }
    }
    __syncthreads();
    if (w == 0) {
        float x = rl[lane];
        float m = x;
        #pragma unroll
        for (int o = 16; o; o >>= 1) m = fmaxf(m, __shfl_xor_sync(0xFFFFFFFFu, m, o));
        float s = expf(x - m);
        #pragma unroll
        for (int o = 16; o; o >>= 1) s += __shfl_xor_sync(0xFFFFFFFFu, s, o);
        if (lane == 0) { g_pm[blockIdx.x] = m; g_ps[blockIdx.x] = s; }
    }
}

// ===== K3c: every block merges the 1000 partials (L2-hot) -> write logp =====
__global__ void k3c_logp(float* __restrict__ out) {
    const int NB = 1000;
    int tid = threadIdx.x, lane = tid & 31;
    float m = g_pm[tid], s = g_ps[tid];         // tid < 256 <= NB always valid
    for (int i = tid + 256; i < NB; i += 256) {
        float m2 = g_pm[i], s2 = g_ps[i];
        float M = fmaxf(m, m2);
        s = s * expf(m - M) + s2 * expf(m2 - M);
        m = M;
    }
    #pragma unroll
    for (int o = 16; o; o >>= 1) {
        float m2 = __shfl_xor_sync(0xFFFFFFFFu, m, o);
        float s2 = __shfl_xor_sync(0xFFFFFFFFu, s, o);
        float M = fmaxf(m, m2);
        s = s * expf(m - M) + s2 * expf(m2 - M);
        m = M;
    }
    __shared__ float sm[8], ss[8];
    __shared__ float s_logZ;
    if (lane == 0) { sm[tid >> 5] = m; ss[tid >> 5] = s; }
    __syncthreads();
    if (tid == 0) {
        float M = sm[0], S = ss[0];
        #pragma unroll
        for (int i = 1; i < 8; i++) {
            float M2 = fmaxf(M, sm[i]);
            S = S * expf(M - M2) + ss[i] * expf(sm[i] - M2);
            M = M2;
        }
        s_logZ = M + logf(S);
    }
    __syncthreads();
    int idx = blockIdx.x * 256 + tid;
    out[idx] = g_logits[idx] - s_logZ;
}

extern "C" void kernel_launch(void* const* d_in, const int* in_sizes, int n_in,
                              void* d_out, int out_size) {
    const float* h    = (const float*)d_in[1];
    const float* enc  = (const float*)d_in[2];
    const float* Wihf = (const float*)d_in[6];
    const float* Whhf = (const float*)d_in[7];
    const float* bihf = (const float*)d_in[8];
    const float* bhhf = (const float*)d_in[9];
    const float* Wihb = (const float*)d_in[10];
    const float* Whhb = (const float*)d_in[11];
    const float* bihb = (const float*)d_in[12];
    const float* bhhb = (const float*)d_in[13];
    const float* outW = (const float*)d_in[14];
    const float* outb = (const float*)d_in[15];
    float* out = (float*)d_out;

    k1_partial<<<BB * LCH, 256>>>(enc);                    // 1024 blocks
    k1b_finalize<<<256, 256>>>(h, out);                    // c, hT, attn fill
    k2_gru<<<128, 256>>>(h, Wihf, Whhf, bihf, bhhf,
                         Wihb, Whhb, bihb, bhhb, out);     // h_new
    k3a_logits<<<1000, 256>>>(outW, outb, out);            // logits + partials
    k3c_logp<<<125, 256>>>(out);                           // logp
}

// round 2
// speedup vs baseline: 1.5428x; 1.5428x over previous
#include <cuda_runtime.h>
#include <math.h>

#define BB   32
#define LL   2048
#define HH   512
#define H2   1024
#define VV   32000
#define LCH  64
#define LPB  (LL / LCH)          // 32 rows per chunk

// ---- scratch (device globals; all written deterministically each launch) ----
__device__ float g_partial[LCH][BB * H2];   // 64 x 32768 partial column sums (8 MB)
__device__ float g_cT[H2][BB];              // relu(mean) context, transposed
__device__ float g_hT[2][HH][BB];           // h transposed per direction
__device__ float g_logits[VV];
__device__ float g_pm[1024];
__device__ float g_ps[1024];

// =============== K1: partial column sums of encoder_out (256 MB stream) =====
__global__ void __launch_bounds__(256) k1_partial(const float* __restrict__ enc) {
    int b  = blockIdx.x >> 6;          // /LCH
    int ch = blockIdx.x & (LCH - 1);
    int t  = threadIdx.x;              // 0..255 -> 256 float4 = 1024 floats/row
    const float4* p = (const float4*)enc + ((size_t)b * LL + (size_t)ch * LPB) * (H2 / 4);
    float4 a0 = make_float4(0.f, 0.f, 0.f, 0.f), a1 = a0, a2 = a0, a3 = a0;
    #pragma unroll 1
    for (int l = 0; l < LPB; l += 8) {
        float4 v0 = __ldcs(&p[(size_t)(l + 0) * 256 + t]);
        float4 v1 = __ldcs(&p[(size_t)(l + 1) * 256 + t]);
        float4 v2 = __ldcs(&p[(size_t)(l + 2) * 256 + t]);
        float4 v3 = __ldcs(&p[(size_t)(l + 3) * 256 + t]);
        float4 v4 = __ldcs(&p[(size_t)(l + 4) * 256 + t]);
        float4 v5 = __ldcs(&p[(size_t)(l + 5) * 256 + t]);
        float4 v6 = __ldcs(&p[(size_t)(l + 6) * 256 + t]);
        float4 v7 = __ldcs(&p[(size_t)(l + 7) * 256 + t]);
        a0.x += v0.x + v4.x; a0.y += v0.y + v4.y; a0.z += v0.z + v4.z; a0.w += v0.w + v4.w;
        a1.x += v1.x + v5.x; a1.y += v1.y + v5.y; a1.z += v1.z + v5.z; a1.w += v1.w + v5.w;
        a2.x += v2.x + v6.x; a2.y += v2.y + v6.y; a2.z += v2.z + v6.z; a2.w += v2.w + v6.w;
        a3.x += v3.x + v7.x; a3.y += v3.y + v7.y; a3.z += v3.z + v7.z; a3.w += v3.w + v7.w;
    }
    float4 s;
    s.x = (a0.x + a1.x) + (a2.x + a3.x);
    s.y = (a0.y + a1.y) + (a2.y + a3.y);
    s.z = (a0.z + a1.z) + (a2.z + a3.z);
    s.w = (a0.w + a1.w) + (a2.w + a3.w);
    ((float4*)(g_partial[ch] + b * H2))[t] = s;
}

// ====== K1b: finalize c (relu(mean), transposed), transpose h, fill attn ====
__global__ void k1b_finalize(const float* __restrict__ h, float* __restrict__ out) {
    int idx = blockIdx.x * 256 + threadIdx.x;      // 0..65535
    // attn_weights output: uniform 1/L
    out[VV + 2 * BB * HH + idx] = 1.0f / (float)LL;
    if (idx < BB * H2) {
        float s = 0.f;
        #pragma unroll 8
        for (int ch = 0; ch < LCH; ch++) s += g_partial[ch][idx];
        s *= (1.0f / (float)LL);
        if (s < 0.f) s = 0.f;
        int b = idx >> 10, d = idx & (H2 - 1);
        g_cT[d][b] = s;
        // transpose h: idx over [2][32][512]
        int dir = idx >> 14, bb = (idx >> 9) & 31, u = idx & (HH - 1);
        g_hT[dir][u][bb] = h[idx];
    }
}

// ===== K2: fused GRU, K-split x2: two warps per (dir,u), combine in smem ====
__global__ void __launch_bounds__(128) k2_gru(
        const float* __restrict__ h,
        const float* __restrict__ Wihf, const float* __restrict__ Whhf,
        const float* __restrict__ bihf, const float* __restrict__ bhhf,
        const float* __restrict__ Wihb, const float* __restrict__ Whhb,
        const float* __restrict__ bihb, const float* __restrict__ bhhb,
        float* __restrict__ out) {
    __shared__ float sp[2][4][32];       // [pairLocal][gr,gz,in,hn][lane]
    int lane = threadIdx.x & 31;
    int w    = threadIdx.x >> 5;         // 0..3
    int pairLocal = w >> 1;
    int half = w & 1;
    int p    = blockIdx.x * 2 + pairLocal;    // 0..1023
    int dir  = p >> 9;
    int u    = p & (HH - 1);
    const float* Wih = dir ? Wihb : Wihf;
    const float* Whh = dir ? Whhb : Whhf;
    const float* bih = dir ? bihb : bihf;
    const float* bhh = dir ? bhhb : bhhf;

    float gr = 0.f, gz = 0.f, gin = 0.f, ghn = 0.f;
    // input-hidden: this warp covers k in [half*512, half*512+512)
    {
        const float4* Wr = (const float4*)(Wih + (size_t)u * H2) + half * 128;
        const float4* Wz = (const float4*)(Wih + (size_t)(HH + u) * H2) + half * 128;
        const float4* Wn = (const float4*)(Wih + (size_t)(2 * HH + u) * H2) + half * 128;
        int kb = half * 512;
        #pragma unroll 8
        for (int k4 = 0; k4 < 128; k4++) {
            float c0 = g_cT[kb + k4 * 4 + 0][lane];
            float c1 = g_cT[kb + k4 * 4 + 1][lane];
            float c2 = g_cT[kb + k4 * 4 + 2][lane];
            float c3 = g_cT[kb + k4 * 4 + 3][lane];
            float4 wr = __ldg(Wr + k4), wz = __ldg(Wz + k4), wn = __ldg(Wn + k4);
            gr  += c0 * wr.x + c1 * wr.y + c2 * wr.z + c3 * wr.w;
            gz  += c0 * wz.x + c1 * wz.y + c2 * wz.z + c3 * wz.w;
            gin += c0 * wn.x + c1 * wn.y + c2 * wn.z + c3 * wn.w;
        }
    }
    // hidden-hidden: this warp covers k in [half*256, half*256+256)
    {
        const float4* Vr = (const float4*)(Whh + (size_t)u * HH) + half * 64;
        const float4* Vz = (const float4*)(Whh + (size_t)(HH + u) * HH) + half * 64;
        const float4* Vn = (const float4*)(Whh + (size_t)(2 * HH + u) * HH) + half * 64;
        int kb = half * 256;
        #pragma unroll 8
        for (int k4 = 0; k4 < 64; k4++) {
            float h0 = g_hT[dir][kb + k4 * 4 + 0][lane];
            float h1 = g_hT[dir][kb + k4 * 4 + 1][lane];
            float h2 = g_hT[dir][kb + k4 * 4 + 2][lane];
            float h3 = g_hT[dir][kb + k4 * 4 + 3][lane];
            float4 vr = __ldg(Vr + k4), vz = __ldg(Vz + k4), vn = __ldg(Vn + k4);
            gr  += h0 * vr.x + h1 * vr.y + h2 * vr.z + h3 * vr.w;
            gz  += h0 * vz.x + h1 * vz.y + h2 * vz.z + h3 * vz.w;
            ghn += h0 * vn.x + h1 * vn.y + h2 * vn.z + h3 * vn.w;
        }
    }
    if (half) {
        sp[pairLocal][0][lane] = gr;
        sp[pairLocal][1][lane] = gz;
        sp[pairLocal][2][lane] = gin;
        sp[pairLocal][3][lane] = ghn;
    }
    __syncthreads();
    if (!half) {
        gr  += sp[pairLocal][0][lane] + bih[u] + bhh[u];
        gz  += sp[pairLocal][1][lane] + bih[HH + u] + bhh[HH + u];
        gin += sp[pairLocal][2][lane] + bih[2 * HH + u];
        ghn += sp[pairLocal][3][lane] + bhh[2 * HH + u];
        float r = 1.f / (1.f + expf(-gr));
        float z = 1.f / (1.f + expf(-gz));
        float n = tanhf(gin + r * ghn);
        float hold = h[dir * BB * HH + lane * HH + u];
        out[VV + dir * BB * HH + lane * HH + u] = (1.f - z) * n + z * hold;
    }
}

// ===== K3a: logits GEMV (131 MB stream) + per-block online (max, sumexp) ====
__global__ void k3a_logits(const float* __restrict__ outW,
                           const float* __restrict__ outb,
                           const float* __restrict__ dout) {
    __shared__ float sv[H2];
    __shared__ float rl[32];
    int tid = threadIdx.x, lane = tid & 31, w = tid >> 5;
    // stage v = c_out[31] = [h_f[31], h_b[31]] from the h_new output region
    for (int i = tid; i < H2; i += 256) {
        int dir = i >> 9, uu = i & (HH - 1);
        sv[i] = dout[VV + dir * BB * HH + 31 * HH + uu];
    }
    __syncthreads();
    int r0 = blockIdx.x * 32 + w * 4;
    const float4* vp = (const float4*)sv;
    #pragma unroll 1
    for (int ri = 0; ri < 4; ri++) {
        int r = r0 + ri;
        const float4* wp = (const float4*)(outW + (size_t)r * H2);
        float acc = 0.f;
        #pragma unroll
        for (int i = 0; i < 8; i++) {
            float4 a = __ldcs(wp + i * 32 + lane);
            float4 v = vp[i * 32 + lane];
            acc += a.x * v.x + a.y * v.y + a.z * v.z + a.w * v.w;
        }
        #pragma unroll
        for (int o = 16; o; o >>= 1) acc += __shfl_down_sync(0xFFFFFFFFu, acc, o);
        if (lane == 0) {
            float lg = acc + outb[r];
            g_logits[r] = lg;
            rl[w * 4 + ri] = lg;
        }
    }
    __syncthreads();
    if (w == 0) {
        float x = rl[lane];
        float m = x;
        #pragma unroll
        for (int o = 16; o; o >>= 1) m = fmaxf(m, __shfl_xor_sync(0xFFFFFFFFu, m, o));
        float s = expf(x - m);
        #pragma unroll
        for (int o = 16; o; o >>= 1) s += __shfl_xor_sync(0xFFFFFFFFu, s, o);
        if (lane == 0) { g_pm[blockIdx.x] = m; g_ps[blockIdx.x] = s; }
    }
}

// ===== K3c: every block merges the 1000 partials (L2-hot) -> write logp =====
__global__ void k3c_logp(float* __restrict__ out) {
    const int NB = 1000;
    int tid = threadIdx.x, lane = tid & 31;
    float m = g_pm[tid], s = g_ps[tid];         // tid < 256 <= NB always valid
    for (int i = tid + 256; i < NB; i += 256) {
        float m2 = g_pm[i], s2 = g_ps[i];
        float M = fmaxf(m, m2);
        s = s * expf(m - M) + s2 * expf(m2 - M);
        m = M;
    }
    #pragma unroll
    for (int o = 16; o; o >>= 1) {
        float m2 = __shfl_xor_sync(0xFFFFFFFFu, m, o);
        float s2 = __shfl_xor_sync(0xFFFFFFFFu, s, o);
        float M = fmaxf(m, m2);
        s = s * expf(m - M) + s2 * expf(m2 - M);
        m = M;
    }
    __shared__ float sm[8], ss[8];
    __shared__ float s_logZ;
    if (lane == 0) { sm[tid >> 5] = m; ss[tid >> 5] = s; }
    __syncthreads();
    if (tid == 0) {
        float M = sm[0], S = ss[0];
        #pragma unroll
        for (int i = 1; i < 8; i++) {
            float M2 = fmaxf(M, sm[i]);
            S = S * expf(M - M2) + ss[i] * expf(sm[i] - M2);
            M = M2;
        }
        s_logZ = M + logf(S);
    }
    __syncthreads();
    int idx = blockIdx.x * 256 + tid;
    out[idx] = g_logits[idx] - s_logZ;
}

extern "C" void kernel_launch(void* const* d_in, const int* in_sizes, int n_in,
                              void* d_out, int out_size) {
    const float* h    = (const float*)d_in[1];
    const float* enc  = (const float*)d_in[2];
    const float* Wihf = (const float*)d_in[6];
    const float* Whhf = (const float*)d_in[7];
    const float* bihf = (const float*)d_in[8];
    const float* bhhf = (const float*)d_in[9];
    const float* Wihb = (const float*)d_in[10];
    const float* Whhb = (const float*)d_in[11];
    const float* bihb = (const float*)d_in[12];
    const float* bhhb = (const float*)d_in[13];
    const float* outW = (const float*)d_in[14];
    const float* outb = (const float*)d_in[15];
    float* out = (float*)d_out;

    k1_partial<<<BB * LCH, 256>>>(enc);                    // 2048 blocks
    k1b_finalize<<<256, 256>>>(h, out);                    // c, hT, attn fill
    k2_gru<<<512, 128>>>(h, Wihf, Whhf, bihf, bhhf,
                         Wihb, Whhb, bihb, bhhb, out);     // h_new
    k3a_logits<<<1000, 256>>>(outW, outb, out);            // logits + partials
    k3c_logp<<<125, 256>>>(out);                           // logp
}

// round 3
// speedup vs baseline: 1.7728x; 1.1490x over previous
#include <cuda_runtime.h>
#include <math.h>

#define BB   32
#define LL   2048
#define HH   512
#define H2   1024
#define VV   32000
#define NB   256
#define GB   88                  // GEMV blocks in P3
#define RB   (NB - GB)           // 168 reduction blocks
#define NWG  (GB * 8)            // 704 GEMV warps

// ---- scratch (device globals; written deterministically each launch) ----
__device__ float g_part31[NB][H2];          // P1 partials for batch 31 (1 MB)
__device__ float g_c31[H2];                 // relu(mean) context, batch 31
__device__ float g_v[H2];                   // c_out[31] = [h_f31, h_b31]
__device__ float g_partial2[31][32][H2];    // rest-reduction partials (4 MB)
__device__ float g_cT[H2][BB];              // context transposed
__device__ float g_hT[2][HH][BB];           // h transposed
__device__ float g_logits[VV];
__device__ float g_pm[NWG];
__device__ float g_ps[NWG];
__device__ float g_logZ;

// ---- self-resetting grid barrier (sense-reversal on generation counter) ----
__device__ volatile unsigned g_gen = 0;
__device__ unsigned g_cnt = 0;

__device__ __forceinline__ void gbar() {
    __syncthreads();
    if (threadIdx.x == 0) {
        unsigned gen = g_gen;
        __threadfence();
        if (atomicAdd(&g_cnt, 1u) == NB - 1) {
            g_cnt = 0;
            __threadfence();
            g_gen = gen + 1;
        } else {
            while (g_gen == gen) { }
        }
        __threadfence();
    }
    __syncthreads();
}

__device__ __forceinline__ void f4acc(float4& a, const float4 v) {
    a.x += v.x; a.y += v.y; a.z += v.z; a.w += v.w;
}

__global__ void __launch_bounds__(256, 2) fused_decoder(
        const float* __restrict__ h,    const float* __restrict__ enc,
        const float* __restrict__ Wihf, const float* __restrict__ Whhf,
        const float* __restrict__ bihf, const float* __restrict__ bhhf,
        const float* __restrict__ Wihb, const float* __restrict__ Whhb,
        const float* __restrict__ bihb, const float* __restrict__ bhhb,
        const float* __restrict__ outW, const float* __restrict__ outb,
        float* __restrict__ out) {
    __shared__ float sv[H2];
    const int bid = blockIdx.x, tid = threadIdx.x;
    const int lane = tid & 31, w = tid >> 5;

    // =============== P1: reduce encoder_out[b=31] (8 MB) + attn fill ========
    {
        const float4* p = (const float4*)enc + ((size_t)31 * LL + bid * 8) * 256;
        float4 a = make_float4(0.f, 0.f, 0.f, 0.f);
        #pragma unroll
        for (int l = 0; l < 8; l++) f4acc(a, __ldcs(&p[(size_t)l * 256 + tid]));
        ((float4*)g_part31[bid])[tid] = a;
        out[VV + 2 * BB * HH + bid * 256 + tid] = 1.0f / (float)LL;
    }
    gbar();

    // =============== P2a: finalize c31 =====================================
    if (bid < 4) {
        int col = bid * 256 + tid;
        float s = 0.f;
        #pragma unroll 8
        for (int p = 0; p < NB; p++) s += g_part31[p][col];
        s *= (1.0f / (float)LL);
        g_c31[col] = s < 0.f ? 0.f : s;
    }
    gbar();

    // =============== P2b: GRU for batch 31 only -> g_v =====================
    {
        int gw = bid * 8 + w;                // 0..2047
        if (gw < 1024) {
            int dir = gw >> 9, u = gw & (HH - 1);
            const float* Wih = dir ? Wihb : Wihf;
            const float* Whh = dir ? Whhb : Whhf;
            const float* bih = dir ? bihb : bihf;
            const float* bhh = dir ? bhhb : bhhf;
            const float4* c4 = (const float4*)g_c31;
            const float4* h4 = (const float4*)(h + dir * BB * HH + 31 * HH);
            float gr = 0.f, gz = 0.f, gin = 0.f, ghn = 0.f;
            {
                const float4* Wr = (const float4*)(Wih + (size_t)u * H2);
                const float4* Wz = (const float4*)(Wih + (size_t)(HH + u) * H2);
                const float4* Wn = (const float4*)(Wih + (size_t)(2 * HH + u) * H2);
                #pragma unroll
                for (int i = 0; i < 8; i++) {
                    int k4 = i * 32 + lane;
                    float4 c = c4[k4];
                    float4 wr = __ldg(Wr + k4), wz = __ldg(Wz + k4), wn = __ldg(Wn + k4);
                    gr  += c.x * wr.x + c.y * wr.y + c.z * wr.z + c.w * wr.w;
                    gz  += c.x * wz.x + c.y * wz.y + c.z * wz.z + c.w * wz.w;
                    gin += c.x * wn.x + c.y * wn.y + c.z * wn.z + c.w * wn.w;
                }
            }
            {
                const float4* Vr = (const float4*)(Whh + (size_t)u * HH);
                const float4* Vz = (const float4*)(Whh + (size_t)(HH + u) * HH);
                const float4* Vn = (const float4*)(Whh + (size_t)(2 * HH + u) * HH);
                #pragma unroll
                for (int i = 0; i < 4; i++) {
                    int k4 = i * 32 + lane;
                    float4 hv = __ldg(h4 + k4);
                    float4 vr = __ldg(Vr + k4), vz = __ldg(Vz + k4), vn = __ldg(Vn + k4);
                    gr  += hv.x * vr.x + hv.y * vr.y + hv.z * vr.z + hv.w * vr.w;
                    gz  += hv.x * vz.x + hv.y * vz.y + hv.z * vz.z + hv.w * vz.w;
                    ghn += hv.x * vn.x + hv.y * vn.y + hv.z * vn.z + hv.w * vn.w;
                }
            }
            #pragma unroll
            for (int o = 16; o; o >>= 1) {
                gr  += __shfl_down_sync(0xFFFFFFFFu, gr, o);
                gz  += __shfl_down_sync(0xFFFFFFFFu, gz, o);
                gin += __shfl_down_sync(0xFFFFFFFFu, gin, o);
                ghn += __shfl_down_sync(0xFFFFFFFFu, ghn, o);
            }
            if (lane == 0) {
                gr  += bih[u] + bhh[u];
                gz  += bih[HH + u] + bhh[HH + u];
                gin += bih[2 * HH + u];
                ghn += bhh[2 * HH + u];
                float r = 1.f / (1.f + expf(-gr));
                float z = 1.f / (1.f + expf(-gz));
                float n = tanhf(gin + r * ghn);
                float hold = h[dir * BB * HH + 31 * HH + u];
                g_v[dir * HH + u] = (1.f - z) * n + z * hold;
            }
        }
    }
    gbar();

    // =============== P3: vocab GEMV (131 MB) || rest-reduce (248 MB) =======
    if (bid < GB) {
        for (int i = tid; i < H2; i += 256) sv[i] = g_v[i];
        __syncthreads();
        int gw = bid * 8 + w;                // 0..703
        const float4* vp = (const float4*)sv;
        float m = -INFINITY, s = 0.f;
        for (int r = gw; r < VV; r += NWG) {
            const float4* wp = (const float4*)(outW + (size_t)r * H2);
            float acc = 0.f;
            #pragma unroll
            for (int i = 0; i < 8; i++) {
                float4 a = __ldcs(wp + i * 32 + lane);
                float4 v = vp[i * 32 + lane];
                acc += a.x * v.x + a.y * v.y + a.z * v.z + a.w * v.w;
            }
            #pragma unroll
            for (int o = 16; o; o >>= 1) acc += __shfl_xor_sync(0xFFFFFFFFu, acc, o);
            float lg = acc + __ldg(outb + r);
            if (lane == 0) g_logits[r] = lg;
            float M = fmaxf(m, lg);
            s = s * expf(m - M) + expf(lg - M);
            m = M;
        }
        if (lane == 0) { g_pm[gw] = m; g_ps[gw] = s; }
    } else {
        int rb = bid - GB;                   // 0..167
        for (int c = rb; c < 31 * 32; c += RB) {
            int b = c >> 5, ch = c & 31;
            const float4* p = (const float4*)enc + ((size_t)b * LL + ch * 64) * 256;
            float4 a0 = make_float4(0.f, 0.f, 0.f, 0.f), a1 = a0, a2 = a0, a3 = a0;
            #pragma unroll 1
            for (int l = 0; l < 64; l += 8) {
                float4 v0 = __ldcs(&p[(size_t)(l + 0) * 256 + tid]);
                float4 v1 = __ldcs(&p[(size_t)(l + 1) * 256 + tid]);
                float4 v2 = __ldcs(&p[(size_t)(l + 2) * 256 + tid]);
                float4 v3 = __ldcs(&p[(size_t)(l + 3) * 256 + tid]);
                float4 v4 = __ldcs(&p[(size_t)(l + 4) * 256 + tid]);
                float4 v5 = __ldcs(&p[(size_t)(l + 5) * 256 + tid]);
                float4 v6 = __ldcs(&p[(size_t)(l + 6) * 256 + tid]);
                float4 v7 = __ldcs(&p[(size_t)(l + 7) * 256 + tid]);
                f4acc(a0, v0); f4acc(a0, v4);
                f4acc(a1, v1); f4acc(a1, v5);
                f4acc(a2, v2); f4acc(a2, v6);
                f4acc(a3, v3); f4acc(a3, v7);
            }
            float4 s4;
            s4.x = (a0.x + a1.x) + (a2.x + a3.x);
            s4.y = (a0.y + a1.y) + (a2.y + a3.y);
            s4.z = (a0.z + a1.z) + (a2.z + a3.z);
            s4.w = (a0.w + a1.w) + (a2.w + a3.w);
            ((float4*)g_partial2[b][ch])[tid] = s4;
        }
    }
    gbar();

    // =============== P4a: finalize cT / hT + merge logZ ====================
    {
        int idx = bid * 256 + tid;           // 0..65535
        if (idx < BB * H2) {
            int b = idx >> 10, col = idx & (H2 - 1);
            float s;
            if (b < 31) {
                s = 0.f;
                #pragma unroll 8
                for (int ch = 0; ch < 32; ch++) s += g_partial2[b][ch][col];
                s *= (1.0f / (float)LL);
                if (s < 0.f) s = 0.f;
            } else {
                s = g_c31[col];
            }
            g_cT[col][b] = s;
        } else {
            int j = idx - BB * H2;           // over [2][32][512]
            int dir = j >> 14, bb2 = (j >> 9) & 31, u = j & (HH - 1);
            g_hT[dir][u][bb2] = h[j];
        }
        if (bid == 0 && w == 0) {
            float m = -INFINITY, s = 0.f;
            for (int i = lane; i < NWG; i += 32) {
                float m2 = g_pm[i], s2 = g_ps[i];
                float M = fmaxf(m, m2);
                s = s * expf(m - M) + s2 * expf(m2 - M);
                m = M;
            }
            #pragma unroll
            for (int o = 16; o; o >>= 1) {
                float m2 = __shfl_xor_sync(0xFFFFFFFFu, m, o);
                float s2 = __shfl_xor_sync(0xFFFFFFFFu, s, o);
                float M = fmaxf(m, m2);
                s = s * expf(m - M) + s2 * expf(m2 - M);
                m = M;
            }
            if (lane == 0) g_logZ = m + logf(s);
        }
    }
    gbar();

    // =============== P4b: full GRU (all batches) + write logp ==============
    {
        int gw = bid * 8 + w;                // 0..2047
        if (gw < 1024) {
            int dir = gw >> 9, u = gw & (HH - 1);
            const float* Wih = dir ? Wihb : Wihf;
            const float* Whh = dir ? Whhb : Whhf;
            const float* bih = dir ? bihb : bihf;
            const float* bhh = dir ? bhhb : bhhf;
            float gr = bih[u] + bhh[u];
            float gz = bih[HH + u] + bhh[HH + u];
            float gin = bih[2 * HH + u];
            float ghn = bhh[2 * HH + u];
            {
                const float4* Wr = (const float4*)(Wih + (size_t)u * H2);
                const float4* Wz = (const float4*)(Wih + (size_t)(HH + u) * H2);
                const float4* Wn = (const float4*)(Wih + (size_t)(2 * HH + u) * H2);
                #pragma unroll 8
                for (int k4 = 0; k4 < H2 / 4; k4++) {
                    float c0 = g_cT[k4 * 4 + 0][lane];
                    float c1 = g_cT[k4 * 4 + 1][lane];
                    float c2 = g_cT[k4 * 4 + 2][lane];
                    float c3 = g_cT[k4 * 4 + 3][lane];
                    float4 wr = __ldg(Wr + k4), wz = __ldg(Wz + k4), wn = __ldg(Wn + k4);
                    gr  += c0 * wr.x + c1 * wr.y + c2 * wr.z + c3 * wr.w;
                    gz  += c0 * wz.x + c1 * wz.y + c2 * wz.z + c3 * wz.w;
                    gin += c0 * wn.x + c1 * wn.y + c2 * wn.z + c3 * wn.w;
                }
            }
            {
                const float4* Vr = (const float4*)(Whh + (size_t)u * HH);
                const float4* Vz = (const float4*)(Whh + (size_t)(HH + u) * HH);
                const float4* Vn = (const float4*)(Whh + (size_t)(2 * HH + u) * HH);
                #pragma unroll 8
                for (int k4 = 0; k4 < HH / 4; k4++) {
                    float h0 = g_hT[dir][k4 * 4 + 0][lane];
                    float h1 = g_hT[dir][k4 * 4 + 1][lane];
                    float h2 = g_hT[dir][k4 * 4 + 2][lane];
                    float h3 = g_hT[dir][k4 * 4 + 3][lane];
                    float4 vr = __ldg(Vr + k4), vz = __ldg(Vz + k4), vn = __ldg(Vn + k4);
                    gr  += h0 * vr.x + h1 * vr.y + h2 * vr.z + h3 * vr.w;
                    gz  += h0 * vz.x + h1 * vz.y + h2 * vz.z + h3 * vz.w;
                    ghn += h0 * vn.x + h1 * vn.y + h2 * vn.z + h3 * vn.w;
                }
            }
            float r = 1.f / (1.f + expf(-gr));
            float z = 1.f / (1.f + expf(-gz));
            float n = tanhf(gin + r * ghn);
            float hold = h[dir * BB * HH + lane * HH + u];
            out[VV + dir * BB * HH + lane * HH + u] = (1.f - z) * n + z * hold;
        } else {
            int idx = (gw - 1024) * 32 + lane;
            if (idx < VV) out[idx] = __ldg(&g_logits[idx]) - g_logZ;
        }
    }
}

extern "C" void kernel_launch(void* const* d_in, const int* in_sizes, int n_in,
                              void* d_out, int out_size) {
    const float* h    = (const float*)d_in[1];
    const float* enc  = (const float*)d_in[2];
    const float* Wihf = (const float*)d_in[6];
    const float* Whhf = (const float*)d_in[7];
    const float* bihf = (const float*)d_in[8];
    const float* bhhf = (const float*)d_in[9];
    const float* Wihb = (const float*)d_in[10];
    const float* Whhb = (const float*)d_in[11];
    const float* bihb = (const float*)d_in[12];
    const float* bhhb = (const float*)d_in[13];
    const float* outW = (const float*)d_in[14];
    const float* outb = (const float*)d_in[15];
    float* out = (float*)d_out;

    fused_decoder<<<NB, 256>>>(h, enc, Wihf, Whhf, bihf, bhhf,
                               Wihb, Whhb, bihb, bhhb, outW, outb, out);
}

// round 4
// speedup vs baseline: 1.9618x; 1.1066x over previous
#include <cuda_runtime.h>
#include <math.h>

#define BB   32
#define LL   2048
#define HH   512
#define H2   1024
#define VV   32000
#define NB   512
#define GB   176                 // GEMV-group blocks
#define RB   (NB - GB)           // 336 reduction blocks
#define NWG  (GB * 8)            // 1408 GEMV warps

// ---- scratch (device globals; written deterministically each launch) ----
__device__ float g_part31[GB][H2];          // batch-31 partials
__device__ float g_c31[H2];                 // relu(mean) context, batch 31
__device__ float g_v[H2];                   // c_out[31]
__device__ float g_partial2[31][32][H2];    // rest-reduction partials (4 MB)
__device__ float g_cT[H2][BB];              // context transposed
__device__ float g_hT[2][HH][BB];           // h transposed
__device__ float g_logits[VV];
__device__ float g_pm[NWG];
__device__ float g_ps[NWG];
__device__ float g_logZ;

// ---- barriers (sense-reversal on generation counters) ----
__device__ volatile unsigned g_genA = 0;  __device__ unsigned g_cntA = 0;  // full grid
__device__ volatile unsigned g_genG = 0;  __device__ unsigned g_cntG = 0;  // GEMV group

__device__ __forceinline__ void barrier_n(volatile unsigned* gen, unsigned* cnt, unsigned n) {
    __syncthreads();
    if (threadIdx.x == 0) {
        unsigned g = *gen;
        __threadfence();
        if (atomicAdd(cnt, 1u) == n - 1) {
            *cnt = 0;
            __threadfence();
            *gen = g + 1;
        } else {
            while (*gen == g) { }
        }
        __threadfence();
    }
    __syncthreads();
}

__device__ __forceinline__ void f4acc(float4& a, const float4 v) {
    a.x += v.x; a.y += v.y; a.z += v.z; a.w += v.w;
}

__global__ void __launch_bounds__(256, 4) fused_decoder(
        const float* __restrict__ h,    const float* __restrict__ enc,
        const float* __restrict__ Wihf, const float* __restrict__ Whhf,
        const float* __restrict__ bihf, const float* __restrict__ bhhf,
        const float* __restrict__ Wihb, const float* __restrict__ Whhb,
        const float* __restrict__ bihb, const float* __restrict__ bhhb,
        const float* __restrict__ outW, const float* __restrict__ outb,
        float* __restrict__ out) {
    __shared__ float sv[H2];
    __shared__ float sp[4][4][32];
    const int bid = blockIdx.x, tid = threadIdx.x;
    const int lane = tid & 31, w = tid >> 5;

    if (bid < GB) {
        // ====== GEMV group: prologue (batch-31 context -> v), then out_W stream
        // P1: reduce encoder_out[b=31] (8 MB over 176 blocks)
        {
            const float4* e4 = (const float4*)enc + (size_t)31 * LL * 256;
            float4 a = make_float4(0.f, 0.f, 0.f, 0.f);
            #pragma unroll 4
            for (int row = bid; row < LL; row += GB)
                f4acc(a, __ldcs(&e4[(size_t)row * 256 + tid]));
            ((float4*)g_part31[bid])[tid] = a;
        }
        barrier_n(&g_genG, &g_cntG, GB);
        // P2a: finalize c31
        if (bid < 4) {
            int col = bid * 256 + tid;
            float s = 0.f;
            #pragma unroll 8
            for (int p = 0; p < GB; p++) s += g_part31[p][col];
            s *= (1.0f / (float)LL);
            g_c31[col] = s < 0.f ? 0.f : s;
        }
        barrier_n(&g_genG, &g_cntG, GB);
        // P2b: GRU for batch 31 only -> g_v (warp per (dir,u), K over lanes)
        {
            int gw = bid * 8 + w;            // 0..1407
            if (gw < 1024) {
                int dir = gw >> 9, u = gw & (HH - 1);
                const float* Wih = dir ? Wihb : Wihf;
                const float* Whh = dir ? Whhb : Whhf;
                const float* bih = dir ? bihb : bihf;
                const float* bhh = dir ? bhhb : bhhf;
                const float4* c4 = (const float4*)g_c31;
                const float4* h4 = (const float4*)(h + dir * BB * HH + 31 * HH);
                float gr = 0.f, gz = 0.f, gin = 0.f, ghn = 0.f;
                const float4* Wr = (const float4*)(Wih + (size_t)u * H2);
                const float4* Wz = (const float4*)(Wih + (size_t)(HH + u) * H2);
                const float4* Wn = (const float4*)(Wih + (size_t)(2 * HH + u) * H2);
                #pragma unroll
                for (int i = 0; i < 8; i++) {
                    int k4 = i * 32 + lane;
                    float4 c = c4[k4];
                    float4 wr = __ldg(Wr + k4), wz = __ldg(Wz + k4), wn = __ldg(Wn + k4);
                    gr  += c.x * wr.x + c.y * wr.y + c.z * wr.z + c.w * wr.w;
                    gz  += c.x * wz.x + c.y * wz.y + c.z * wz.z + c.w * wz.w;
                    gin += c.x * wn.x + c.y * wn.y + c.z * wn.z + c.w * wn.w;
                }
                const float4* Vr = (const float4*)(Whh + (size_t)u * HH);
                const float4* Vz = (const float4*)(Whh + (size_t)(HH + u) * HH);
                const float4* Vn = (const float4*)(Whh + (size_t)(2 * HH + u) * HH);
                #pragma unroll
                for (int i = 0; i < 4; i++) {
                    int k4 = i * 32 + lane;
                    float4 hv = __ldg(h4 + k4);
                    float4 vr = __ldg(Vr + k4), vz = __ldg(Vz + k4), vn = __ldg(Vn + k4);
                    gr  += hv.x * vr.x + hv.y * vr.y + hv.z * vr.z + hv.w * vr.w;
                    gz  += hv.x * vz.x + hv.y * vz.y + hv.z * vz.z + hv.w * vz.w;
                    ghn += hv.x * vn.x + hv.y * vn.y + hv.z * vn.z + hv.w * vn.w;
                }
                #pragma unroll
                for (int o = 16; o; o >>= 1) {
                    gr  += __shfl_down_sync(0xFFFFFFFFu, gr, o);
                    gz  += __shfl_down_sync(0xFFFFFFFFu, gz, o);
                    gin += __shfl_down_sync(0xFFFFFFFFu, gin, o);
                    ghn += __shfl_down_sync(0xFFFFFFFFu, ghn, o);
                }
                if (lane == 0) {
                    gr  += bih[u] + bhh[u];
                    gz  += bih[HH + u] + bhh[HH + u];
                    gin += bih[2 * HH + u];
                    ghn += bhh[2 * HH + u];
                    float r = 1.f / (1.f + expf(-gr));
                    float z = 1.f / (1.f + expf(-gz));
                    float n = tanhf(gin + r * ghn);
                    float hold = h[dir * BB * HH + 31 * HH + u];
                    g_v[dir * HH + u] = (1.f - z) * n + z * hold;
                }
            }
        }
        barrier_n(&g_genG, &g_cntG, GB);
        // P3-GEMV: vocab logits (131 MB) + online softmax partials
        {
            for (int i = tid; i < H2; i += 256) sv[i] = g_v[i];
            __syncthreads();
            int gw = bid * 8 + w;            // 0..1407
            const float4* vp = (const float4*)sv;
            float m = -INFINITY, s = 0.f;
            for (int r = gw; r < VV; r += NWG) {
                const float4* wp = (const float4*)(outW + (size_t)r * H2);
                float acc = 0.f;
                #pragma unroll
                for (int i = 0; i < 8; i++) {
                    float4 a = __ldcs(wp + i * 32 + lane);
                    float4 v = vp[i * 32 + lane];
                    acc += a.x * v.x + a.y * v.y + a.z * v.z + a.w * v.w;
                }
                #pragma unroll
                for (int o = 16; o; o >>= 1) acc += __shfl_xor_sync(0xFFFFFFFFu, acc, o);
                float lg = acc + __ldg(outb + r);
                if (lane == 0) g_logits[r] = lg;
                float M = fmaxf(m, lg);
                s = s * expf(m - M) + expf(lg - M);
                m = M;
            }
            if (lane == 0) { g_pm[gw] = m; g_ps[gw] = s; }
        }
    } else {
        // ====== Reduction group: stream batches 0..30 (248 MB) immediately ==
        int rb = bid - GB;                   // 0..335
        for (int c = rb; c < 31 * 32; c += RB) {
            int b = c >> 5, ch = c & 31;
            const float4* p = (const float4*)enc + ((size_t)b * LL + ch * 64) * 256;
            float4 a0 = make_float4(0.f, 0.f, 0.f, 0.f), a1 = a0, a2 = a0, a3 = a0;
            #pragma unroll 1
            for (int l = 0; l < 64; l += 8) {
                float4 v0 = __ldcs(&p[(size_t)(l + 0) * 256 + tid]);
                float4 v1 = __ldcs(&p[(size_t)(l + 1) * 256 + tid]);
                float4 v2 = __ldcs(&p[(size_t)(l + 2) * 256 + tid]);
                float4 v3 = __ldcs(&p[(size_t)(l + 3) * 256 + tid]);
                float4 v4 = __ldcs(&p[(size_t)(l + 4) * 256 + tid]);
                float4 v5 = __ldcs(&p[(size_t)(l + 5) * 256 + tid]);
                float4 v6 = __ldcs(&p[(size_t)(l + 6) * 256 + tid]);
                float4 v7 = __ldcs(&p[(size_t)(l + 7) * 256 + tid]);
                f4acc(a0, v0); f4acc(a0, v4);
                f4acc(a1, v1); f4acc(a1, v5);
                f4acc(a2, v2); f4acc(a2, v6);
                f4acc(a3, v3); f4acc(a3, v7);
            }
            float4 s4;
            s4.x = (a0.x + a1.x) + (a2.x + a3.x);
            s4.y = (a0.y + a1.y) + (a2.y + a3.y);
            s4.z = (a0.z + a1.z) + (a2.z + a3.z);
            s4.w = (a0.w + a1.w) + (a2.w + a3.w);
            ((float4*)g_partial2[b][ch])[tid] = s4;
        }
    }
    barrier_n(&g_genA, &g_cntA, NB);

    // =============== P4a: finalize cT / hT, attn fill, merge logZ ==========
    {
        int idx = bid * 256 + tid;           // 0..131071
        if (idx < BB * H2) {
            int b = idx >> 10, col = idx & (H2 - 1);
            float s;
            if (b < 31) {
                s = 0.f;
                #pragma unroll 8
                for (int ch = 0; ch < 32; ch++) s += g_partial2[b][ch][col];
                s *= (1.0f / (float)LL);
                if (s < 0.f) s = 0.f;
            } else {
                s = g_c31[col];
            }
            g_cT[col][b] = s;
        } else if (idx < 2 * BB * H2) {
            int j = idx - BB * H2;           // over [2][32][512]
            int dir = j >> 14, bb2 = (j >> 9) & 31, u = j & (HH - 1);
            g_hT[dir][u][bb2] = h[j];
            // attn_weights output: uniform 1/L (65536 floats)
            out[VV + 2 * BB * HH + (idx - BB * H2)] = 1.0f / (float)LL;
            out[VV + 2 * BB * HH + idx] = 1.0f / (float)LL;
        }
        if (bid == 0 && w == 0) {
            float m = -INFINITY, s = 0.f;
            for (int i = lane; i < NWG; i += 32) {
                float m2 = g_pm[i], s2 = g_ps[i];
                float M = fmaxf(m, m2);
                s = s * expf(m - M) + s2 * expf(m2 - M);
                m = M;
            }
            #pragma unroll
            for (int o = 16; o; o >>= 1) {
                float m2 = __shfl_xor_sync(0xFFFFFFFFu, m, o);
                float s2 = __shfl_xor_sync(0xFFFFFFFFu, s, o);
                float M = fmaxf(m, m2);
                s = s * expf(m - M) + s2 * expf(m2 - M);
                m = M;
            }
            if (lane == 0) g_logZ = m + logf(s);
        }
    }
    barrier_n(&g_genA, &g_cntA, NB);

    // ====== P4b: full GRU (K-split x2 across paired warps) + write logp ====
    if (bid < 256) {
        int p    = bid * 4 + (w & 3);        // 0..1023
        int half = w >> 2;
        int dir  = p >> 9, u = p & (HH - 1);
        const float* Wih = dir ? Wihb : Wihf;
        const float* Whh = dir ? Whhb : Whhf;
        const float* bih = dir ? bihb : bihf;
        const float* bhh = dir ? bhhb : bhhf;
        float gr = 0.f, gz = 0.f, gin = 0.f, ghn = 0.f;
        {
            const float4* Wr = (const float4*)(Wih + (size_t)u * H2) + half * 128;
            const float4* Wz = (const float4*)(Wih + (size_t)(HH + u) * H2) + half * 128;
            const float4* Wn = (const float4*)(Wih + (size_t)(2 * HH + u) * H2) + half * 128;
            int kb = half * 512;
            #pragma unroll 4
            for (int k4 = 0; k4 < 128; k4++) {
                float c0 = g_cT[kb + k4 * 4 + 0][lane];
                float c1 = g_cT[kb + k4 * 4 + 1][lane];
                float c2 = g_cT[kb + k4 * 4 + 2][lane];
                float c3 = g_cT[kb + k4 * 4 + 3][lane];
                float4 wr = __ldg(Wr + k4), wz = __ldg(Wz + k4), wn = __ldg(Wn + k4);
                gr  += c0 * wr.x + c1 * wr.y + c2 * wr.z + c3 * wr.w;
                gz  += c0 * wz.x + c1 * wz.y + c2 * wz.z + c3 * wz.w;
                gin += c0 * wn.x + c1 * wn.y + c2 * wn.z + c3 * wn.w;
            }
        }
        {
            const float4* Vr = (const float4*)(Whh + (size_t)u * HH) + half * 64;
            const float4* Vz = (const float4*)(Whh + (size_t)(HH + u) * HH) + half * 64;
            const float4* Vn = (const float4*)(Whh + (size_t)(2 * HH + u) * HH) + half * 64;
            int kb = half * 256;
            #pragma unroll 4
            for (int k4 = 0; k4 < 64; k4++) {
                float h0 = g_hT[dir][kb + k4 * 4 + 0][lane];
                float h1 = g_hT[dir][kb + k4 * 4 + 1][lane];
                float h2 = g_hT[dir][kb + k4 * 4 + 2][lane];
                float h3 = g_hT[dir][kb + k4 * 4 + 3][lane];
                float4 vr = __ldg(Vr + k4), vz = __ldg(Vz + k4), vn = __ldg(Vn + k4);
                gr  += h0 * vr.x + h1 * vr.y + h2 * vr.z + h3 * vr.w;
                gz  += h0 * vz.x + h1 * vz.y + h2 * vz.z + h3 * vz.w;
                ghn += h0 * vn.x + h1 * vn.y + h2 * vn.z + h3 * vn.w;
            }
        }
        if (half) {
            sp[w & 3][0][lane] = gr;
            sp[w & 3][1][lane] = gz;
            sp[w & 3][2][lane] = gin;
            sp[w & 3][3][lane] = ghn;
        }
        __syncthreads();
        if (!half) {
            gr  += sp[w & 3][0][lane] + bih[u] + bhh[u];
            gz  += sp[w & 3][1][lane] + bih[HH + u] + bhh[HH + u];
            gin += sp[w & 3][2][lane] + bih[2 * HH + u];
            ghn += sp[w & 3][3][lane] + bhh[2 * HH + u];
            float r = 1.f / (1.f + expf(-gr));
            float z = 1.f / (1.f + expf(-gz));
            float n = tanhf(gin + r * ghn);
            float hold = h[dir * BB * HH + lane * HH + u];
            out[VV + dir * BB * HH + lane * HH + u] = (1.f - z) * n + z * hold;
        }
    } else {
        int idx = (bid - 256) * 256 + tid;   // 0..65535
        if (idx < VV) out[idx] = __ldg(&g_logits[idx]) - g_logZ;
    }
}

extern "C" void kernel_launch(void* const* d_in, const int* in_sizes, int n_in,
                              void* d_out, int out_size) {
    const float* h    = (const float*)d_in[1];
    const float* enc  = (const float*)d_in[2];
    const float* Wihf = (const float*)d_in[6];
    const float* Whhf = (const float*)d_in[7];
    const float* bihf = (const float*)d_in[8];
    const float* bhhf = (const float*)d_in[9];
    const float* Wihb = (const float*)d_in[10];
    const float* Whhb = (const float*)d_in[11];
    const float* bihb = (const float*)d_in[12];
    const float* bhhb = (const float*)d_in[13];
    const float* outW = (const float*)d_in[14];
    const float* outb = (const float*)d_in[15];
    float* out = (float*)d_out;

    fused_decoder<<<NB, 256>>>(h, enc, Wihf, Whhf, bihf, bhhf,
                               Wihb, Whhb, bihb, bhhb, outW, outb, out);
}